// round 5
// baseline (speedup 1.0000x reference)
#include <cuda_runtime.h>
#include <cstdint>

// ---------------- problem constants ----------------
#define NBLK   128
#define NTHR   256
#define NBATCH 128
#define KPH    3
#define MAXPER 48
#define MAXTOK 144
#define CTOK   145
#define HD     512
#define VOC    8000
#define BOSTOK 1
#define EOSTOK 2

// ---------------- scratch offsets (floats) ----------------
#define O_WZ    0u
#define O_MEM   49152u
#define O_CK    1622016u
#define O_CV    3194880u
#define O_QP    4767744u
#define O_KP    4898816u
#define O_VP    5029888u
#define O_SA    5160960u
#define O_P1    5226496u
#define O_X1    5488640u
#define O_CQP   5554176u
#define O_CA    5816320u
#define O_P2    5881856u
#define O_X2    6144000u
#define O_W1P   6209536u
#define O_ACT   6733824u
#define O_W2P   6995968u
#define O_GATE  7520256u
#define O_KC    7520384u
#define O_VC    17023104u
#define F_TOTAL 26525824u

// d_out float32 layout: tokens[128*144] | genm[128*144] | bounds[128*3] | hiddens[144*128*512]
#define OUT_GENM   18432
#define OUT_BOUNDS 36864
#define OUT_HID    37248

__device__ static __align__(128) float g_f[F_TOTAL];
__device__ static unsigned long long g_amax[MAXTOK * NBATCH];
// g_i: [0,384) active, [384,512) pos, [512,640) tip, [640,768) phr, [768,896) done, [896,1024) nxt
__device__ static int g_i[1024];
__device__ static unsigned g_count;
__device__ static volatile unsigned g_gen;

// ---------------- helpers ----------------
__device__ __forceinline__ float gelu_tanh(float x) {
    float x3 = x * x * x;
    return 0.5f * x * (1.0f + tanhf(0.7978845608028654f * (x + 0.044715f * x3)));
}
__device__ __forceinline__ float wred(float p) {
    p += __shfl_xor_sync(0xffffffffu, p, 16);
    p += __shfl_xor_sync(0xffffffffu, p, 8);
    p += __shfl_xor_sync(0xffffffffu, p, 4);
    p += __shfl_xor_sync(0xffffffffu, p, 2);
    p += __shfl_xor_sync(0xffffffffu, p, 1);
    return p;
}
__device__ __forceinline__ unsigned long long umax64(unsigned long long a, unsigned long long b) {
    return a > b ? a : b;
}

// grid-wide barrier (sense reversal). All NBLK blocks co-resident (NBLK <= #SM).
__device__ __forceinline__ void gsync() {
    __syncthreads();
    if (threadIdx.x == 0) {
        unsigned gen = g_gen;
        __threadfence();
        if (atomicAdd(&g_count, 1u) == (unsigned)(NBLK - 1)) {
            g_count = 0u;
            __threadfence();
            g_gen = gen + 1u;
        } else {
            while (g_gen == gen) __nanosleep(64);
        }
        __threadfence();
    }
    __syncthreads();
}

// ---------------- 128x32 output tile core (BK=32) ----------------
__device__ __forceinline__ void run_tile(
    const float* __restrict__ A, const int* __restrict__ gidx, int lda,
    const float* __restrict__ W, int ldw, int wcol,
    int kOff, int kChunk, float* sA, float* sW, float acc[4][4])
{
    const int tid = threadIdx.x;
    const int arow = tid >> 3, ak4 = (tid & 7) << 2;
    const int rg4 = (tid >> 3) << 2, cg4 = (tid & 7) << 2;
#pragma unroll
    for (int i = 0; i < 4; i++)
#pragma unroll
        for (int j = 0; j < 4; j++) acc[i][j] = 0.f;

    for (int kt = 0; kt < kChunk; kt += 32) {
#pragma unroll
        for (int i = 0; i < 4; i++) {
            int r = arow + (i << 5);
            int rr = gidx ? gidx[r] : r;
            float4 v = *(const float4*)(A + (size_t)rr * lda + kOff + kt + ak4);
            sA[(ak4 + 0) * 132 + r] = v.x;
            sA[(ak4 + 1) * 132 + r] = v.y;
            sA[(ak4 + 2) * 132 + r] = v.z;
            sA[(ak4 + 3) * 132 + r] = v.w;
        }
        *(float4*)&sW[arow * 32 + ak4] =
            *(const float4*)(W + (size_t)(kOff + kt + arow) * ldw + wcol + ak4);
        __syncthreads();
#pragma unroll
        for (int kk = 0; kk < 32; kk++) {
            float4 av = *(const float4*)&sA[kk * 132 + rg4];
            float4 wv = *(const float4*)&sW[kk * 32 + cg4];
            acc[0][0] += av.x * wv.x; acc[0][1] += av.x * wv.y; acc[0][2] += av.x * wv.z; acc[0][3] += av.x * wv.w;
            acc[1][0] += av.y * wv.x; acc[1][1] += av.y * wv.y; acc[1][2] += av.y * wv.z; acc[1][3] += av.y * wv.w;
            acc[2][0] += av.z * wv.x; acc[2][1] += av.z * wv.y; acc[2][2] += av.z * wv.z; acc[2][3] += av.z * wv.w;
            acc[3][0] += av.w * wv.x; acc[3][1] += av.w * wv.y; acc[3][2] += av.w * wv.z; acc[3][3] += av.w * wv.w;
        }
        __syncthreads();
    }
}

__device__ __forceinline__ void store_tile(float* __restrict__ C, int ldc, int colBase,
                                           const float acc[4][4])
{
    const int rg4 = (threadIdx.x >> 3) << 2, cg4 = (threadIdx.x & 7) << 2;
#pragma unroll
    for (int i = 0; i < 4; i++)
        *(float4*)(C + (size_t)(rg4 + i) * ldc + colBase + cg4) =
            make_float4(acc[i][0], acc[i][1], acc[i][2], acc[i][3]);
}

// ---------------- the persistent mega-kernel ----------------
__global__ void __launch_bounds__(NTHR, 1) mega_kernel(
    const float* __restrict__ z_seq, const float* __restrict__ z_w,
    const float* __restrict__ Wl2d, const float* __restrict__ temb,
    const float* __restrict__ Wq,  const float* __restrict__ Wk,
    const float* __restrict__ Wv,  const float* __restrict__ Wo,
    const float* __restrict__ Wcq, const float* __restrict__ Wck,
    const float* __restrict__ Wcv, const float* __restrict__ Wco,
    const float* __restrict__ W1,  const float* __restrict__ W2,
    const float* __restrict__ Wout, float* __restrict__ out)
{
    __shared__ float sm[32 * 132 + 32 * 32];
    float* sA = sm;
    float* sW = sm + 32 * 132;

    const int tid = threadIdx.x;
    const int bx  = blockIdx.x;
    const int gid = bx * NTHR + tid;
    const int gsz = NBLK * NTHR;   // 32768
    float acc[4][4];

    float* wz  = g_f + O_WZ;
    float* mem = g_f + O_MEM;
    float* ckb = g_f + O_CK;
    float* cvb = g_f + O_CV;
    float* qp  = g_f + O_QP;
    float* kp  = g_f + O_KP;
    float* vp  = g_f + O_VP;
    float* sab = g_f + O_SA;
    float* p1  = g_f + O_P1;
    float* x1  = g_f + O_X1;
    float* cqp = g_f + O_CQP;
    float* cab = g_f + O_CA;
    float* p2  = g_f + O_P2;
    float* x2  = g_f + O_X2;
    float* w1p = g_f + O_W1P;
    float* act = g_f + O_ACT;
    float* w2p = g_f + O_W2P;
    float* gate = g_f + O_GATE;
    float* kc  = g_f + O_KC;
    float* vc  = g_f + O_VC;
    int* nxt = g_i + 896;

    // ---- phase: init ----
    for (int i = gid; i < 49152; i += gsz) wz[i] = z_w[i >> 7] * z_seq[i];
    for (int i = gid; i < OUT_HID; i += gsz) out[i] = 0.f;
    for (int i = gid; i < MAXTOK * NBATCH; i += gsz) g_amax[i] = 0ull;
    if (gid < 384) g_i[gid] = (z_w[gid] > 0.01f) ? 1 : 0;
    if (gid < 128) {
        g_i[384 + gid] = 0;                          // pos
        g_i[512 + gid] = 0;                          // tip
        g_i[640 + gid] = 0;                          // phr
        int a0 = (z_w[gid * 3] > 0.01f) ? 1 : 0;
        g_i[768 + gid] = !a0;                        // done
        g_i[896 + gid] = BOSTOK;                     // nxt
        gate[gid] = a0 ? 1.f : 0.f;
    }
    gsync();

    // ---- phase: memories = wz[384,128] @ Wl2d[128,4096] ----
    for (int tile = bx; tile < 384; tile += NBLK) {
        int by = tile >> 7, cx = tile & 127;
        run_tile(wz + (size_t)by * 128 * 128, nullptr, 128, Wl2d, 4096, cx * 32,
                 0, 128, sA, sW, acc);
        store_tile(mem + (size_t)by * 128 * 4096, 4096, cx * 32, acc);
    }
    gsync();

    // ---- phase: ck/cv = mem[3072,512] @ Wck/Wcv ----
    for (int tile = bx; tile < 768; tile += NBLK) {
        int isv = tile >= 384;
        int idx = isv ? tile - 384 : tile;
        int by = idx >> 4, cx = idx & 15;
        const float* W_ = isv ? Wcv : Wck;
        float* C_ = isv ? cvb : ckb;
        run_tile(mem + (size_t)by * 128 * 512, nullptr, 512, W_, 512, cx * 32,
                 0, 512, sA, sW, acc);
        store_tile(C_ + (size_t)by * 128 * 512, 512, cx * 32, acc);
    }
    gsync();

    // ================= decode loop =================
    for (int t = 0; t < MAXTOK; t++) {
        // ---- QKV: A = temb[nxt], split-K2 (chunk 256); partials -> qp/kp/vp ----
        for (int tile = bx; tile < 96; tile += NBLK) {
            int cx = tile % 48, ks = tile / 48;
            int sel = cx >> 4;
            const float* W_ = (sel == 0) ? Wq : ((sel == 1) ? Wk : Wv);
            float* C_ = (sel == 0) ? qp : ((sel == 1) ? kp : vp);
            run_tile(temb, nxt, 512, W_, 512, (cx & 15) * 32, ks * 256, 256, sA, sW, acc);
            store_tile(C_ + ks * 65536, 512, (cx & 15) * 32, acc);
        }
        gsync();

        // ---- attention: finalize q/k/v, write cache slot t, softmax-attend ----
        {
            int wid = tid >> 5, lane = tid & 31;
            int gw = bx * 8 + wid;               // 0..1023
            int b = gw >> 3, h = gw & 7;
            int off = b * 512 + h * 64 + lane * 2;
            float2 qv  = *(const float2*)(qp + off);
            float2 q1  = *(const float2*)(qp + 65536 + off);
            qv.x += q1.x; qv.y += q1.y;
            float2 kv2 = *(const float2*)(kp + off);
            float2 k1  = *(const float2*)(kp + 65536 + off);
            kv2.x += k1.x; kv2.y += k1.y;
            float2 vv2 = *(const float2*)(vp + off);
            float2 v1  = *(const float2*)(vp + 65536 + off);
            vv2.x += v1.x; vv2.y += v1.y;
            size_t cbase = ((size_t)(b * 8 + h) * CTOK) * 64 + lane * 2;
            *(float2*)(kc + cbase + (size_t)t * 64) = kv2;
            *(float2*)(vc + cbase + (size_t)t * 64) = vv2;

            float* sc = sm + wid * 152;
            const float* Kp = kc + cbase;
            for (int s = 0; s < t; s++) {
                float2 kv = *(const float2*)(Kp + (size_t)s * 64);
                float p = wred(qv.x * kv.x + qv.y * kv.y);
                if (lane == 0) sc[s] = p * 0.125f;
            }
            {
                float p = wred(qv.x * kv2.x + qv.y * kv2.y);
                if (lane == 0) sc[t] = p * 0.125f;
            }
            __syncwarp();
            int n = t + 1;
            float mx = -1e30f;
            for (int s = lane; s < n; s += 32) mx = fmaxf(mx, sc[s]);
            for (int o = 16; o; o >>= 1) mx = fmaxf(mx, __shfl_xor_sync(0xffffffffu, mx, o));
            float sum = 0.f;
            for (int s = lane; s < n; s += 32) {
                float e = expf(sc[s] - mx);
                sc[s] = e;
                sum += e;
            }
            for (int o = 16; o; o >>= 1) sum += __shfl_xor_sync(0xffffffffu, sum, o);
            float inv = 1.0f / sum;
            __syncwarp();
            const float* Vp = vc + cbase;
            float a0 = 0.f, a1 = 0.f;
            for (int s = 0; s < t; s++) {
                float p = sc[s] * inv;
                float2 vv = *(const float2*)(Vp + (size_t)s * 64);
                a0 += p * vv.x;
                a1 += p * vv.y;
            }
            {
                float p = sc[t] * inv;
                a0 += p * vv2.x;
                a1 += p * vv2.y;
            }
            *(float2*)(sab + off) = make_float2(a0, a1);
        }
        gsync();

        // ---- Wo: sa @ Wo, split-K4 -> p1 ----
        for (int tile = bx; tile < 64; tile += NBLK) {
            int cx = tile & 15, ks = tile >> 4;
            run_tile(sab, nullptr, 512, Wo, 512, cx * 32, ks * 128, 128, sA, sW, acc);
            store_tile(p1 + ks * 65536, 512, cx * 32, acc);
        }
        gsync();

        // ---- x1 = temb[nxt] + sum4(p1) ----
        for (int i = gid; i < 65536; i += gsz) {
            int r = i >> 9;
            float v = temb[(size_t)nxt[r] * 512 + (i & 511)];
            v += ((p1[i] + p1[65536 + i]) + (p1[131072 + i] + p1[196608 + i]));
            x1[i] = v;
        }
        gsync();

        // ---- cq: x1 @ Wcq, split-K4 -> cqp ----
        for (int tile = bx; tile < 64; tile += NBLK) {
            int cx = tile & 15, ks = tile >> 4;
            run_tile(x1, nullptr, 512, Wcq, 512, cx * 32, ks * 128, 128, sA, sW, acc);
            store_tile(cqp + ks * 65536, 512, cx * 32, acc);
        }
        gsync();

        // ---- cross-attention over 8 memories ----
        {
            int wid = tid >> 5, lane = tid & 31;
            int gw = bx * 8 + wid;
            int b = gw >> 3, h = gw & 7;
            int off = b * 512 + h * 64 + lane * 2;
            float2 qv = make_float2(0.f, 0.f);
#pragma unroll
            for (int j = 0; j < 4; j++) {
                float2 p = *(const float2*)(cqp + j * 65536 + off);
                qv.x += p.x; qv.y += p.y;
            }
            int phr = g_i[640 + b];
            int i = phr < 2 ? phr : 2;
            float g = gate[b];
            size_t base = (size_t)((b * 3 + i) * 8) * 512 + h * 64 + lane * 2;
            const float* Kp = ckb + base;
            const float* Vp = cvb + base;
            float s[8], mx = -1e30f;
#pragma unroll
            for (int m = 0; m < 8; m++) {
                float2 kv = *(const float2*)(Kp + m * 512);
                s[m] = wred(qv.x * kv.x + qv.y * kv.y) * 0.125f;
                mx = fmaxf(mx, s[m]);
            }
            float sum = 0.f;
#pragma unroll
            for (int m = 0; m < 8; m++) { s[m] = expf(s[m] - mx); sum += s[m]; }
            float inv = 1.0f / sum;
            float a0 = 0.f, a1 = 0.f;
#pragma unroll
            for (int m = 0; m < 8; m++) {
                float2 vv = *(const float2*)(Vp + m * 512);
                a0 += s[m] * vv.x;
                a1 += s[m] * vv.y;
            }
            *(float2*)(cab + off) = make_float2(a0 * inv * g, a1 * inv * g);
        }
        gsync();

        // ---- Wco: ca @ Wco, split-K4 -> p2 ----
        for (int tile = bx; tile < 64; tile += NBLK) {
            int cx = tile & 15, ks = tile >> 4;
            run_tile(cab, nullptr, 512, Wco, 512, cx * 32, ks * 128, 128, sA, sW, acc);
            store_tile(p2 + ks * 65536, 512, cx * 32, acc);
        }
        gsync();

        // ---- x2 = x1 + sum4(p2) ----
        for (int i = gid; i < 65536; i += gsz)
            x2[i] = x1[i] + ((p2[i] + p2[65536 + i]) + (p2[131072 + i] + p2[196608 + i]));
        gsync();

        // ---- W1: x2 @ W1 [512,2048], split-K2 -> w1p ----
        for (int tile = bx; tile < 128; tile += NBLK) {
            int cx = tile & 63, ks = tile >> 6;
            run_tile(x2, nullptr, 512, W1, 2048, cx * 32, ks * 256, 256, sA, sW, acc);
            store_tile(w1p + ks * 262144, 2048, cx * 32, acc);
        }
        gsync();

        // ---- act = gelu(sum2(w1p)) ----
        for (int i = gid; i < 262144; i += gsz)
            act[i] = gelu_tanh(w1p[i] + w1p[262144 + i]);
        gsync();

        // ---- W2: act[128,2048] @ W2[2048,512], split-K8 -> w2p ----
        for (int tile = bx; tile < 128; tile += NBLK) {
            int cx = tile & 15, ks = tile >> 4;
            run_tile(act, nullptr, 2048, W2, 512, cx * 32, ks * 256, 256, sA, sW, acc);
            store_tile(w2p + ks * 65536, 512, cx * 32, acc);
        }
        gsync();

        // ---- hid = x2 + sum8(w2p) -> out hiddens slab ----
        float* hid = out + OUT_HID + (size_t)t * 65536;
        for (int i = gid; i < 65536; i += gsz) {
            float v = x2[i];
            v += ((w2p[i] + w2p[65536 + i]) + (w2p[131072 + i] + w2p[196608 + i]))
               + ((w2p[262144 + i] + w2p[327680 + i]) + (w2p[393216 + i] + w2p[458752 + i]));
            hid[i] = v;
        }
        gsync();

        // ---- logits + fused deterministic argmax ----
        for (int tile = bx; tile < 250; tile += NBLK) {
            run_tile(hid, nullptr, 512, Wout, VOC, tile * 32, 0, 512, sA, sW, acc);
            const int rg4 = (tid >> 3) << 2, cg4 = (tid & 7) << 2;
#pragma unroll
            for (int i = 0; i < 4; i++) {
                int row = rg4 + i;
                unsigned long long best = 0ull;
#pragma unroll
                for (int j = 0; j < 4; j++) {
                    int col = tile * 32 + cg4 + j;
                    unsigned u = __float_as_uint(acc[i][j]);
                    u = (u & 0x80000000u) ? ~u : (u | 0x80000000u);
                    best = umax64(best, ((unsigned long long)u << 32) |
                                        (unsigned)(VOC - 1 - col));
                }
                best = umax64(best, __shfl_xor_sync(0xffffffffu, best, 1));
                best = umax64(best, __shfl_xor_sync(0xffffffffu, best, 2));
                best = umax64(best, __shfl_xor_sync(0xffffffffu, best, 4));
                if ((tid & 7) == 0) atomicMax(&g_amax[t * 128 + row], best);
            }
        }
        gsync();

        // ---- state machine (block 0 only) ----
        if (bx == 0 && tid < 128) {
            int b = tid;
            unsigned long long key = g_amax[t * 128 + b];
            int col = (VOC - 1) - (int)(key & 0xffffffffu);
            int pos = g_i[384 + b], tip = g_i[512 + b], phr = g_i[640 + b], done = g_i[768 + b];
            int live = !done;
            if (live) {
                out[b * MAXTOK + pos] = (float)col;
                out[OUT_GENM + b * MAXTOK + pos] = 1.0f;
            }
            pos += live;
            tip += live;
            int eos = (col == EOSTOK) && (tip >= 1);
            int sw = (eos || (tip >= MAXPER)) && live;
            phr += sw;
            if (sw) tip = 0;
            int cp = phr < 2 ? phr : 2;
            if (sw && phr < KPH) out[OUT_BOUNDS + b * 3 + cp] = (float)pos;
            done = done || (phr >= KPH) || (sw && !g_i[b * 3 + cp]);
            g_i[384 + b] = pos;
            g_i[512 + b] = tip;
            g_i[640 + b] = phr;
            g_i[768 + b] = done;
            g_i[896 + b] = col;
            gate[b] = (g_i[b * 3 + cp] && !done) ? 1.0f : 0.0f;
        }
        gsync();
    }
}

// ---------------- host ----------------
extern "C" void kernel_launch(void* const* d_in, const int* in_sizes, int n_in,
                              void* d_out, int out_size)
{
    (void)in_sizes; (void)n_in; (void)out_size;
    mega_kernel<<<NBLK, NTHR>>>(
        (const float*)d_in[0],  (const float*)d_in[1],  (const float*)d_in[2],
        (const float*)d_in[3],  (const float*)d_in[4],  (const float*)d_in[5],
        (const float*)d_in[6],  (const float*)d_in[7],  (const float*)d_in[8],
        (const float*)d_in[9],  (const float*)d_in[10], (const float*)d_in[11],
        (const float*)d_in[12], (const float*)d_in[13], (const float*)d_in[14],
        (float*)d_out);
}